// round 13
// baseline (speedup 1.0000x reference)
#include <cuda_runtime.h>
#include <cuda_fp16.h>
#include <cstdint>

#define C_IN   64
#define C_OUT  64
#define Hdim   224
#define Wdim   224
#define HW     (Hdim * Wdim)
#define NTHR   448

// B weight smem: u64 units, index = ((tap*4+ks)*8 + wn*4 + nt)*32 + gr*4 + tc
#define WS_BYTES (9 * 4 * 8 * 32 * 8)   // 73728
#define X_OFF    WS_BYTES
// fp16 x ring: 5 slots x [cipair 32 (stride 232 u32)]; halo j=3 (col -1), interior j=4..227, halo j=228
#define PXS    232
#define SLOTU  (32 * PXS)               // 7424 u32
#define NSLOT  5
#define SMEM_TOTAL (X_OFF + NSLOT * SLOTU * 4)   // 222208 B

// packed fp16 ci-pairs of x: [n][cipair 32][h][w]
__device__ __align__(16) uint32_t g_xh[16 * 32 * HW];
// ternary weights, LDS.64-friendly fragment layout (see ternarize)
__device__ __align__(16) unsigned short g_twB[9 * 4 * 8 * 32 * 4];
__device__ float g_alpha[C_OUT];

// ---------------------------------------------------------------- helpers
__device__ __forceinline__ uint32_t smem_u32(const void* p) {
    uint32_t a;
    asm("{ .reg .u64 t; cvta.to.shared.u64 t, %1; cvt.u32.u64 %0, t; }" : "=r"(a) : "l"(p));
    return a;
}
__device__ __forceinline__ void cp16(uint32_t dst, const void* src, int sz) {
    asm volatile("cp.async.cg.shared.global [%0], [%1], 16, %2;"
                 :: "r"(dst), "l"(src), "r"(sz) : "memory");
}
__device__ __forceinline__ uint32_t packh2(float lo, float hi) {
    return (uint32_t)__half_as_ushort(__float2half_rn(lo)) |
           ((uint32_t)__half_as_ushort(__float2half_rn(hi)) << 16);
}
__device__ __forceinline__ void mma_h(float* c, const uint32_t* a, uint32_t b0, uint32_t b1) {
    asm volatile(
        "mma.sync.aligned.m16n8k16.row.col.f32.f16.f16.f32 "
        "{%0,%1,%2,%3}, {%4,%5,%6,%7}, {%8,%9}, {%0,%1,%2,%3};"
        : "+f"(c[0]), "+f"(c[1]), "+f"(c[2]), "+f"(c[3])
        : "r"(a[0]), "r"(a[1]), "r"(a[2]), "r"(a[3]), "r"(b0), "r"(b1));
}

// ---------------------------------------------------------------- prepass: f32 -> packed fp16 pairs
__global__ void __launch_bounds__(256) prepass_kernel(const float* __restrict__ x) {
    int idx = blockIdx.x * 256 + threadIdx.x;
    int u = idx * 4;
    int n = u / (32 * HW);
    int r = u - n * (32 * HW);
    int c = r / HW;
    int p = r - c * HW;
    const float4 a = *(const float4*)(x + ((size_t)(n * 64 + 2 * c) * HW + p));
    const float4 b = *(const float4*)(x + ((size_t)(n * 64 + 2 * c + 1) * HW + p));
    uint4 o;
    o.x = packh2(a.x, b.x);
    o.y = packh2(a.y, b.y);
    o.z = packh2(a.z, b.z);
    o.w = packh2(a.w, b.w);
    *(uint4*)(g_xh + u) = o;
}

// ---------------------------------------------------------------- ternarize
__global__ void ternarize_kernel(const float* __restrict__ weight) {
    __shared__ float red[256], red2[256];
    __shared__ float s_delta, s_alpha;
    const int co = blockIdx.x, tid = threadIdx.x;
    const float* w = weight + co * 576;

    float v0 = (tid < 576) ? w[tid] : 0.0f;
    float v1 = (tid + 256 < 576) ? w[tid + 256] : 0.0f;
    float v2 = (tid + 512 < 576) ? w[tid + 512] : 0.0f;
    float a0 = fabsf(v0), a1 = fabsf(v1), a2 = fabsf(v2);

    red[tid] = a0 + a1 + a2;
    __syncthreads();
    for (int s = 128; s > 0; s >>= 1) { if (tid < s) red[tid] += red[tid + s]; __syncthreads(); }
    if (tid == 0) s_delta = (float)(0.7 / 576.0) * red[0];
    __syncthreads();
    const float delta = s_delta;

    float m0 = (a0 > delta) ? 1.f : 0.f, m1 = (a1 > delta) ? 1.f : 0.f, m2 = (a2 > delta) ? 1.f : 0.f;
    red[tid] = m0 * a0 + m1 * a1 + m2 * a2;
    red2[tid] = m0 + m1 + m2;
    __syncthreads();
    for (int s = 128; s > 0; s >>= 1) {
        if (tid < s) { red[tid] += red[tid + s]; red2[tid] += red2[tid + s]; }
        __syncthreads();
    }
    if (tid == 0) {
        float cnt = red2[0]; if (cnt < 0.5f) cnt = 1.0f;
        s_alpha = fmaxf(red[0] / cnt, 1e-4f);
        g_alpha[co] = s_alpha;
    }
    __syncthreads();

    const int wn = co >> 5, nt = (co >> 3) & 3, grb = co & 7;
#pragma unroll
    for (int q = 0; q < 3; q++) {
        int f = tid + q * 256;
        if (f < 576) {
            float v = (q == 0) ? v0 : (q == 1) ? v1 : v2;
            float t = (v > delta) ? 1.0f : ((v < -delta) ? -1.0f : 0.0f);
            int ci = f / 9, tap = f % 9;     // weight layout [co][ci][kh][kw]
            int ks = ci >> 4, r = ci & 15;
            int word = r >> 3, rr = r & 7;
            int tcb = rr >> 1, e = rr & 1;
            int u64idx = (((tap * 4 + ks) * 8 + wn * 4 + nt) * 32) + grb * 4 + tcb;
            g_twB[u64idx * 4 + word * 2 + e] = __half_as_ushort(__float2half_rn(t));
        }
    }
}

// ---------------------------------------------------------------- row staging (cp.async interior only)
// 32 cipairs x 56 chunks (224 cols / 4) = 1792 chunks = 4 per thread
__device__ __forceinline__ void cp_stage(uint32_t sxa, int n, int row, int tid) {
    const bool rok = (unsigned)row < (unsigned)Hdim;
    const int srow = rok ? row : 0;
    const int sz16 = rok ? 16 : 0;
    const uint32_t slot_b = sxa + (uint32_t)((row + NSLOT * 2) % NSLOT) * (SLOTU * 4);
    const uint32_t* xb = g_xh + (size_t)n * 32 * HW + (size_t)srow * Wdim;
#pragma unroll
    for (int k = 0; k < 4; k++) {
        int idx = tid + k * NTHR;            // 0..1791
        int c = idx / 56;                    // cipair 0..31
        int q = (idx - c * 56) * 4;          // col 0..220
        cp16(slot_b + (uint32_t)(c * PXS + 4 + q) * 4,
             xb + (size_t)c * HW + q, sz16);
    }
    asm volatile("cp.async.commit_group;" ::: "memory");
}

// ---------------------------------------------------------------- conv (persistent)
// grid (148). 448 thr = 14 warps: 7 M-warps (32 px, full 224 row) x 2 N-warps (32 co).
// Each CTA owns a contiguous chunk of the 3584 flattened (n, h) output rows:
// first 32 CTAs take 25 rows, remaining 116 take 24 (32*25 + 116*24 = 3584).
__global__ void __launch_bounds__(NTHR, 1)
conv_kernel(const float* __restrict__ bias, float* __restrict__ out) {
    extern __shared__ char smem[];
    const uint2* B64 = (const uint2*)smem;
    uint32_t* sx = (uint32_t*)(smem + X_OFF);
    const uint32_t wsa = smem_u32(smem);
    const uint32_t sxa = smem_u32(smem + X_OFF);

    const int tid = threadIdx.x, lane = tid & 31, wid = tid >> 5;
    const int gr = lane >> 2, tc = lane & 3;
    const int wm = (wid < 7) ? wid : wid - 7;
    const int wn = (wid < 7) ? 0 : 1;
    const int colb = wm * 32;
    const int bid = blockIdx.x;

    int rs = (bid < 32) ? bid * 25 : 800 + (bid - 32) * 24;
    int re = rs + ((bid < 32) ? 25 : 24);

    // boundary halos (cols -1 and 224) are always zero: init once, all slots
    for (int idx = tid; idx < NSLOT * 64; idx += NTHR) {
        int slot = idx >> 6;
        int c = (idx & 63) >> 1, side = idx & 1;
        sx[slot * SLOTU + c * PXS + 3 + side * 225] = 0;
    }

    // weights -> smem once: 4608 chunks of 16B
    {
#pragma unroll
        for (int k = 0; k < 11; k++) {
            int chunk = tid + k * NTHR;
            if (chunk < 4608)
                cp16(wsa + (uint32_t)chunk * 16, (const char*)g_twB + (size_t)chunk * 16, 16);
        }
        asm volatile("cp.async.commit_group;" ::: "memory");
    }

    float als[4][2], bis[4][2];
#pragma unroll
    for (int nt = 0; nt < 4; nt++) {
        int co = wn * 32 + nt * 8 + 2 * tc;
        als[nt][0] = g_alpha[co];     als[nt][1] = g_alpha[co + 1];
        bis[nt][0] = bias[co];        bis[nt][1] = bias[co + 1];
    }

    while (rs < re) {
        const int n = rs / Hdim;
        const int h0 = rs - n * Hdim;
        const int hend = min(re - n * Hdim, Hdim);   // rows [h0, hend) of image n

        cp_stage(sxa, n, h0 - 1, tid);
        cp_stage(sxa, n, h0,     tid);
        cp_stage(sxa, n, h0 + 1, tid);

        for (int h = h0; h < hend; h++) {
            if (h + 1 < hend) {
                cp_stage(sxa, n, h + 2, tid);
                asm volatile("cp.async.wait_group 1;" ::: "memory");
            } else {
                asm volatile("cp.async.wait_group 0;" ::: "memory");
            }
            __syncthreads();     // rows h-1..h+1 (and weights) visible

            float acc[2][4][4];
#pragma unroll
            for (int mt = 0; mt < 2; mt++)
#pragma unroll
                for (int nt = 0; nt < 4; nt++)
#pragma unroll
                    for (int e = 0; e < 4; e++) acc[mt][nt][e] = 0.0f;

#pragma unroll
            for (int kh = 0; kh < 3; kh++) {
                const uint32_t* slotp = sx + ((h + kh - 1 + NSLOT * 2) % NSLOT) * SLOTU;
#pragma unroll
                for (int kw = 0; kw < 3; kw++) {
                    const uint32_t* ap_base = slotp + tc * PXS + 3 + colb + kw + gr;
                    const uint2* bq0 = B64 + ((((kh * 3 + kw) * 4) * 8 + wn * 4) * 32 + gr * 4 + tc);
#pragma unroll
                    for (int ks = 0; ks < 4; ks++) {
                        const uint32_t* ap = ap_base + (8 * ks) * PXS;
                        const uint2* bq = bq0 + ks * 256;
                        uint32_t A[2][4];
#pragma unroll
                        for (int mt = 0; mt < 2; mt++) {
                            const uint32_t* a = ap + mt * 16;
                            A[mt][0] = a[0];
                            A[mt][1] = a[8];
                            A[mt][2] = a[4 * PXS];
                            A[mt][3] = a[4 * PXS + 8];
                        }
#pragma unroll
                        for (int nt = 0; nt < 4; nt++) {
                            uint2 b = bq[nt * 32];
                            mma_h(acc[0][nt], A[0], b.x, b.y);
                            mma_h(acc[1][nt], A[1], b.x, b.y);
                        }
                    }
                }
            }

            // epilogue
#pragma unroll
            for (int mt = 0; mt < 2; mt++) {
#pragma unroll
                for (int nt = 0; nt < 4; nt++) {
                    int co = wn * 32 + nt * 8 + 2 * tc;
                    int wg = colb + mt * 16 + gr;
                    float* p = out + ((size_t)(n * C_OUT + co)) * HW + (size_t)h * Wdim + wg;
                    p[0]      = acc[mt][nt][0] * als[nt][0] + bis[nt][0];
                    p[HW]     = acc[mt][nt][1] * als[nt][1] + bis[nt][1];
                    p[8]      = acc[mt][nt][2] * als[nt][0] + bis[nt][0];
                    p[HW + 8] = acc[mt][nt][3] * als[nt][1] + bis[nt][1];
                }
            }
            // intra-loop ring safety: next iter writes slot (h+3)%5 ≡ (h-2)%5,
            // disjoint from rows h-1..h+1 read here; skew bounded by per-iter sync.
        }
        __syncthreads();     // segment end: all reads done before next prime overwrites slots
        rs = n * Hdim + hend;
    }
}

extern "C" void kernel_launch(void* const* d_in, const int* in_sizes, int n_in,
                              void* d_out, int out_size) {
    const float* x      = (const float*)d_in[0];
    const float* weight = (const float*)d_in[1];
    const float* bias   = (const float*)d_in[2];
    float* out          = (float*)d_out;

    cudaFuncSetAttribute(conv_kernel, cudaFuncAttributeMaxDynamicSharedMemorySize,
                         SMEM_TOTAL);

    prepass_kernel<<<16 * 32 * HW / 4 / 256, 256>>>(x);
    ternarize_kernel<<<C_OUT, 256>>>(weight);

    conv_kernel<<<148, NTHR, SMEM_TOTAL>>>(bias, out);
}